// round 5
// baseline (speedup 1.0000x reference)
#include <cuda_runtime.h>
#include <cstdint>

#define NB 64
#define NT 4096
#define KP 67
#define NF 134
#define FPAD 136
#define ND 256
#define NC 7
#define TB 64          // timesteps per CTA tile
#define THREADS 256

// scratch for pooled max (relu output >= 0, so 0-init + int atomicMax on float bits is exact)
__device__ float g_pooled[NB * ND];
// normalized lengths (dtype-robust)
__device__ int g_len[NB];

// dynamic smem: Bs[FPAD][ND] then As[TB][FPAD]
#define BS_FLOATS (FPAD * ND)
#define AS_FLOATS (TB * FPAD)
#define SMEM1_BYTES ((BS_FLOATS + AS_FLOATS) * 4)

// ---- prologue: detect int32 vs int64 length buffer, normalize to g_len ----
__global__ void fix_length_kernel(const void* __restrict__ lenraw)
{
    const int*       as32 = (const int*)lenraw;
    const long long* as64 = (const long long*)lenraw;
    // int32 interpretation of an int64 buffer yields 0 (hi words) in odd slots;
    // int64 interpretation of an int32 buffer yields huge packed values.
    bool ok32 = true;
    for (int i = 0; i < NB; i++) {
        int v = as32[i];
        if (v < 1 || v > NT) { ok32 = false; break; }
    }
    for (int i = 0; i < NB; i++)
        g_len[i] = ok32 ? as32[i] : (int)as64[i];
}

__global__ __launch_bounds__(THREADS, 1)
void gemm_pool_kernel(const float* __restrict__ body,
                      const float* __restrict__ hand_r,
                      const float* __restrict__ hand_l,
                      const float* __restrict__ W1,
                      const float* __restrict__ b1)
{
    const int b  = blockIdx.y;
    const int t0 = blockIdx.x * TB;
    const int len = g_len[b];
    if (t0 >= len) return;                      // fully-masked tile: skip (scratch pre-zeroed)

    extern __shared__ float smem[];
    float* Bs = smem;                            // [FPAD][ND]
    float* As = smem + BS_FLOATS;                // [TB][FPAD]
    const int tid = threadIdx.x;

    // ---- load W1 into smem (rows 0..133), zero pad rows 134..135 ----
    {
        const float4* src = (const float4*)W1;
        float4* dst = (float4*)Bs;
        for (int i = tid; i < (NF * ND) / 4; i += THREADS) dst[i] = src[i];
        for (int i = tid; i < (2 * ND) / 4; i += THREADS)
            dst[(NF * ND) / 4 + i] = make_float4(0.f, 0.f, 0.f, 0.f);
    }

    // ---- build gated A tile: As[r][2j],As[r][2j+1] = x*g, y*g ; zero pad cols ----
    for (int idx = tid; idx < TB * KP; idx += THREADS) {
        int r = idx / KP;
        int j = idx - r * KP;
        int t = t0 + r;
        const float* src;
        if (j < 25)       src = body   + ((size_t)b * NT + t) * 75 + 3 * j;
        else if (j < 46)  src = hand_r + ((size_t)b * NT + t) * 63 + 3 * (j - 25);
        else              src = hand_l + ((size_t)b * NT + t) * 63 + 3 * (j - 46);
        float x = src[0], y = src[1], c = src[2];
        float g = (c > 0.1f) ? 1.0f : 0.0f;
        As[r * FPAD + 2 * j]     = x * g;
        As[r * FPAD + 2 * j + 1] = y * g;
    }
    for (int r = tid; r < TB; r += THREADS) {
        As[r * FPAD + 134] = 0.f;
        As[r * FPAD + 135] = 0.f;
    }
    __syncthreads();

    // ---- 8t x 8d micro-tile per thread, packed f32x2 math (pairs along d) ----
    const int tr = tid >> 5;          // 0..7  t-group
    const int tc = tid & 31;          // 0..31 d-group
    const int dbase = tc * 8;

    unsigned long long acc[8][4];
    #pragma unroll
    for (int i = 0; i < 8; i++)
        #pragma unroll
        for (int jj = 0; jj < 4; jj++) acc[i][jj] = 0ull;

    #pragma unroll 1
    for (int k0 = 0; k0 < FPAD; k0 += 4) {
        float4 a4[8];
        #pragma unroll
        for (int i = 0; i < 8; i++)
            a4[i] = *(const float4*)&As[(tr * 8 + i) * FPAD + k0];

        #pragma unroll
        for (int kk = 0; kk < 4; kk++) {
            const int k = k0 + kk;
            ulonglong2 bl = *(const ulonglong2*)&Bs[k * ND + dbase];
            ulonglong2 bh = *(const ulonglong2*)&Bs[k * ND + dbase + 4];
            #pragma unroll
            for (int i = 0; i < 8; i++) {
                float a = (kk == 0) ? a4[i].x : (kk == 1) ? a4[i].y : (kk == 2) ? a4[i].z : a4[i].w;
                unsigned long long ap;
                asm("mov.b64 %0, {%1, %1};" : "=l"(ap) : "f"(a));
                asm("fma.rn.f32x2 %0, %1, %2, %0;" : "+l"(acc[i][0]) : "l"(ap), "l"(bl.x));
                asm("fma.rn.f32x2 %0, %1, %2, %0;" : "+l"(acc[i][1]) : "l"(ap), "l"(bl.y));
                asm("fma.rn.f32x2 %0, %1, %2, %0;" : "+l"(acc[i][2]) : "l"(ap), "l"(bh.x));
                asm("fma.rn.f32x2 %0, %1, %2, %0;" : "+l"(acc[i][3]) : "l"(ap), "l"(bh.y));
            }
        }
    }

    // ---- bias + relu + masked max over this thread's 8 rows ----
    float bsv[8];
    *(float4*)&bsv[0] = *(const float4*)&b1[dbase];
    *(float4*)&bsv[4] = *(const float4*)&b1[dbase + 4];

    float mx[8];
    #pragma unroll
    for (int jj = 0; jj < 8; jj++) mx[jj] = 0.0f;

    #pragma unroll
    for (int i = 0; i < 8; i++) {
        if (t0 + tr * 8 + i < len) {
            #pragma unroll
            for (int jj = 0; jj < 4; jj++) {
                float lo, hi;
                asm("mov.b64 {%0, %1}, %2;" : "=f"(lo), "=f"(hi) : "l"(acc[i][jj]));
                lo = fmaxf(lo + bsv[2 * jj], 0.0f);
                hi = fmaxf(hi + bsv[2 * jj + 1], 0.0f);
                mx[2 * jj]     = fmaxf(mx[2 * jj], lo);
                mx[2 * jj + 1] = fmaxf(mx[2 * jj + 1], hi);
            }
        }
    }

    // ---- CTA reduce across the 8 t-groups, then one atomicMax per d ----
    __syncthreads();                 // everyone done reading As
    float* red = As;                 // reuse: [8][ND]
    #pragma unroll
    for (int jj = 0; jj < 8; jj++) red[tr * ND + dbase + jj] = mx[jj];
    __syncthreads();

    {
        float m = red[tid];
        #pragma unroll
        for (int g = 1; g < 8; g++) m = fmaxf(m, red[g * ND + tid]);
        atomicMax((int*)&g_pooled[b * ND + tid], __float_as_int(m));
    }
}

// ---- BatchNorm (batch stats) + classifier ----
__global__ __launch_bounds__(256, 1)
void bn_cls_kernel(const float* __restrict__ pooled,
                   const float* __restrict__ gamma,
                   const float* __restrict__ beta,
                   const float* __restrict__ Wc,
                   const float* __restrict__ bc,
                   float* __restrict__ out)
{
    extern __shared__ float sb[];    // [NB][ND] bn values
    const int d = threadIdx.x;       // 256 threads == ND

    float v[NB];
    float s = 0.f;
    #pragma unroll
    for (int bb = 0; bb < NB; bb++) { v[bb] = pooled[bb * ND + d]; s += v[bb]; }
    float mean = s * (1.0f / NB);
    float q = 0.f;
    #pragma unroll
    for (int bb = 0; bb < NB; bb++) { float t = v[bb] - mean; q += t * t; }
    float rstd = rsqrtf(q * (1.0f / NB) + 1e-5f);
    float g = gamma[d], be = beta[d];
    #pragma unroll
    for (int bb = 0; bb < NB; bb++) sb[bb * ND + d] = (v[bb] - mean) * rstd * g + be;
    __syncthreads();

    for (int idx = threadIdx.x; idx < NB * NC; idx += 256) {
        int bb = idx / NC, c = idx - bb * NC;
        float sum = bc[c];
        const float* row = &sb[bb * ND];
        #pragma unroll 8
        for (int dd = 0; dd < ND; dd++) sum += row[dd] * Wc[dd * NC + c];
        out[bb * NC + c] = sum;
    }
}

extern "C" void kernel_launch(void* const* d_in, const int* in_sizes, int n_in,
                              void* d_out, int out_size)
{
    const float* body   = (const float*)d_in[0];
    const float* hand_r = (const float*)d_in[1];
    const float* hand_l = (const float*)d_in[2];
    const void*  length = d_in[3];
    const float* W1     = (const float*)d_in[4];
    const float* b1     = (const float*)d_in[5];
    const float* gamma  = (const float*)d_in[6];
    const float* beta   = (const float*)d_in[7];
    const float* Wc     = (const float*)d_in[8];
    const float* bc     = (const float*)d_in[9];
    float* out = (float*)d_out;

    void* pooled_ptr = nullptr;
    cudaGetSymbolAddress(&pooled_ptr, g_pooled);
    cudaMemsetAsync(pooled_ptr, 0, NB * ND * sizeof(float));

    cudaFuncSetAttribute(gemm_pool_kernel,
                         cudaFuncAttributeMaxDynamicSharedMemorySize, SMEM1_BYTES);
    cudaFuncSetAttribute(bn_cls_kernel,
                         cudaFuncAttributeMaxDynamicSharedMemorySize, NB * ND * 4);

    fix_length_kernel<<<1, 1>>>(length);

    dim3 grid(NT / TB, NB);
    gemm_pool_kernel<<<grid, THREADS, SMEM1_BYTES>>>(body, hand_r, hand_l, W1, b1);
    bn_cls_kernel<<<1, 256, NB * ND * 4>>>((const float*)pooled_ptr, gamma, beta, Wc, bc, out);
}

// round 7
// speedup vs baseline: 1.5035x; 1.5035x over previous
#include <cuda_runtime.h>
#include <cstdint>

#define NB 64
#define NT 4096
#define KP 67
#define NF 134
#define FPAD 136
#define ND 256
#define NC 7
#define TB 64          // timesteps per CTA tile
#define THREADS 256

// scratch for pooled max (relu output >= 0, so 0-init + int atomicMax on float bits is exact)
__device__ float g_pooled[NB * ND];
// normalized lengths (dtype-robust)
__device__ int g_len[NB];

// dynamic smem: Bs[FPAD][ND] then As[TB][FPAD]
#define BS_FLOATS (FPAD * ND)
#define AS_FLOATS (TB * FPAD)
#define SMEM1_BYTES ((BS_FLOATS + AS_FLOATS) * 4)

// ---- prologue: detect int32 vs int64 length buffer, normalize to g_len ----
// int32 view of an int64 buffer has 0 in the odd (hi-word) slots; an int32
// buffer read as int32 has all 64 values in [1, NT]. 64 threads + ballot.
__global__ void fix_length_kernel(const void* __restrict__ lenraw)
{
    const int*       as32 = (const int*)lenraw;
    const long long* as64 = (const long long*)lenraw;
    const int i = threadIdx.x;            // 0..63
    int v32 = as32[i];
    bool ok = (v32 >= 1 && v32 <= NT);
    unsigned lo = __ballot_sync(0xffffffffu, i < 32 ? ok : true);
    unsigned hi = __ballot_sync(0xffffffffu, i >= 32 ? ok : true);
    __shared__ unsigned s_lo, s_hi;
    if (i == 0)  s_lo = lo;
    if (i == 32) s_hi = hi;
    __syncthreads();
    bool all32 = (s_lo == 0xffffffffu) && (s_hi == 0xffffffffu);
    g_len[i] = all32 ? v32 : (int)as64[i];
}

__global__ __launch_bounds__(THREADS, 1)
void gemm_pool_kernel(const float* __restrict__ body,
                      const float* __restrict__ hand_r,
                      const float* __restrict__ hand_l,
                      const float* __restrict__ W1,
                      const float* __restrict__ b1)
{
    const int b  = blockIdx.y;
    const int t0 = blockIdx.x * TB;
    const int len = g_len[b];
    if (t0 >= len) return;                      // fully-masked tile: skip (scratch pre-zeroed)

    extern __shared__ float smem[];
    float* Bs = smem;                            // [FPAD][ND]
    float* As = smem + BS_FLOATS;                // [TB][FPAD]
    const int tid = threadIdx.x;

    // ---- load W1 into smem (rows 0..133), zero pad rows 134..135 ----
    {
        const float4* src = (const float4*)W1;
        float4* dst = (float4*)Bs;
        for (int i = tid; i < (NF * ND) / 4; i += THREADS) dst[i] = src[i];
        for (int i = tid; i < (2 * ND) / 4; i += THREADS)
            dst[(NF * ND) / 4 + i] = make_float4(0.f, 0.f, 0.f, 0.f);
    }

    // ---- build gated A tile: As[r][2j],As[r][2j+1] = x*g, y*g ; zero pad cols ----
    for (int idx = tid; idx < TB * KP; idx += THREADS) {
        int r = idx / KP;
        int j = idx - r * KP;
        int t = t0 + r;
        const float* src;
        if (j < 25)       src = body   + ((size_t)b * NT + t) * 75 + 3 * j;
        else if (j < 46)  src = hand_r + ((size_t)b * NT + t) * 63 + 3 * (j - 25);
        else              src = hand_l + ((size_t)b * NT + t) * 63 + 3 * (j - 46);
        float x = src[0], y = src[1], c = src[2];
        float g = (c > 0.1f) ? 1.0f : 0.0f;
        As[r * FPAD + 2 * j]     = x * g;
        As[r * FPAD + 2 * j + 1] = y * g;
    }
    for (int r = tid; r < TB; r += THREADS) {
        As[r * FPAD + 134] = 0.f;
        As[r * FPAD + 135] = 0.f;
    }
    __syncthreads();

    // ---- 8t x 8d micro-tile per thread, packed f32x2 math ----
    // Column mapping: two groups of 4 columns, 16B lane stride -> conflict-free
    //   acc[i][0..1] cover d = dlo..dlo+3, acc[i][2..3] cover d = dhi..dhi+3
    const int tr  = tid >> 5;          // 0..7  t-group (uniform per warp -> A broadcast)
    const int tc  = tid & 31;          // 0..31 d-group
    const int dlo = tc * 4;
    const int dhi = 128 + tc * 4;

    unsigned long long acc[8][4];
    #pragma unroll
    for (int i = 0; i < 8; i++)
        #pragma unroll
        for (int jj = 0; jj < 4; jj++) acc[i][jj] = 0ull;

    #pragma unroll 1
    for (int k0 = 0; k0 < FPAD; k0 += 4) {
        float4 a4[8];
        #pragma unroll
        for (int i = 0; i < 8; i++)
            a4[i] = *(const float4*)&As[(tr * 8 + i) * FPAD + k0];

        #pragma unroll
        for (int kk = 0; kk < 4; kk++) {
            const int k = k0 + kk;
            ulonglong2 bl = *(const ulonglong2*)&Bs[k * ND + dlo];   // lane*16B: no conflicts
            ulonglong2 bh = *(const ulonglong2*)&Bs[k * ND + dhi];
            #pragma unroll
            for (int i = 0; i < 8; i++) {
                float a = (kk == 0) ? a4[i].x : (kk == 1) ? a4[i].y : (kk == 2) ? a4[i].z : a4[i].w;
                unsigned long long ap;
                asm("mov.b64 %0, {%1, %1};" : "=l"(ap) : "f"(a));
                asm("fma.rn.f32x2 %0, %1, %2, %0;" : "+l"(acc[i][0]) : "l"(ap), "l"(bl.x));
                asm("fma.rn.f32x2 %0, %1, %2, %0;" : "+l"(acc[i][1]) : "l"(ap), "l"(bl.y));
                asm("fma.rn.f32x2 %0, %1, %2, %0;" : "+l"(acc[i][2]) : "l"(ap), "l"(bh.x));
                asm("fma.rn.f32x2 %0, %1, %2, %0;" : "+l"(acc[i][3]) : "l"(ap), "l"(bh.y));
            }
        }
    }

    // ---- bias + relu + masked max over this thread's 8 rows ----
    float bsv[8];
    *(float4*)&bsv[0] = *(const float4*)&b1[dlo];
    *(float4*)&bsv[4] = *(const float4*)&b1[dhi];

    float mx[8];
    #pragma unroll
    for (int jj = 0; jj < 8; jj++) mx[jj] = 0.0f;

    #pragma unroll
    for (int i = 0; i < 8; i++) {
        if (t0 + tr * 8 + i < len) {
            #pragma unroll
            for (int jj = 0; jj < 4; jj++) {
                float lo, hi;
                asm("mov.b64 {%0, %1}, %2;" : "=f"(lo), "=f"(hi) : "l"(acc[i][jj]));
                lo = fmaxf(lo + bsv[2 * jj], 0.0f);
                hi = fmaxf(hi + bsv[2 * jj + 1], 0.0f);
                mx[2 * jj]     = fmaxf(mx[2 * jj], lo);
                mx[2 * jj + 1] = fmaxf(mx[2 * jj + 1], hi);
            }
        }
    }

    // ---- CTA reduce across the 8 t-groups, then one atomicMax per d ----
    __syncthreads();                 // everyone done reading As
    float* red = As;                 // reuse: [8][ND]
    #pragma unroll
    for (int jj = 0; jj < 4; jj++) {
        red[tr * ND + dlo + jj] = mx[jj];
        red[tr * ND + dhi + jj] = mx[4 + jj];
    }
    __syncthreads();

    {
        float m = red[tid];
        #pragma unroll
        for (int g = 1; g < 8; g++) m = fmaxf(m, red[g * ND + tid]);
        atomicMax((int*)&g_pooled[b * ND + tid], __float_as_int(m));
    }
}

// ---- BatchNorm (batch stats) + classifier ----
__global__ __launch_bounds__(256, 1)
void bn_cls_kernel(const float* __restrict__ pooled,
                   const float* __restrict__ gamma,
                   const float* __restrict__ beta,
                   const float* __restrict__ Wc,
                   const float* __restrict__ bc,
                   float* __restrict__ out)
{
    extern __shared__ float sb[];    // [NB][ND] bn values
    const int d = threadIdx.x;       // 256 threads == ND

    float v[NB];
    float s = 0.f;
    #pragma unroll
    for (int bb = 0; bb < NB; bb++) { v[bb] = pooled[bb * ND + d]; s += v[bb]; }
    float mean = s * (1.0f / NB);
    float q = 0.f;
    #pragma unroll
    for (int bb = 0; bb < NB; bb++) { float t = v[bb] - mean; q += t * t; }
    float rstd = rsqrtf(q * (1.0f / NB) + 1e-5f);
    float g = gamma[d], be = beta[d];
    #pragma unroll
    for (int bb = 0; bb < NB; bb++) sb[bb * ND + d] = (v[bb] - mean) * rstd * g + be;
    __syncthreads();

    for (int idx = threadIdx.x; idx < NB * NC; idx += 256) {
        int bb = idx / NC, c = idx - bb * NC;
        float sum = bc[c];
        const float* row = &sb[bb * ND];
        #pragma unroll 8
        for (int dd = 0; dd < ND; dd++) sum += row[dd] * Wc[dd * NC + c];
        out[bb * NC + c] = sum;
    }
}

extern "C" void kernel_launch(void* const* d_in, const int* in_sizes, int n_in,
                              void* d_out, int out_size)
{
    const float* body   = (const float*)d_in[0];
    const float* hand_r = (const float*)d_in[1];
    const float* hand_l = (const float*)d_in[2];
    const void*  length = d_in[3];
    const float* W1     = (const float*)d_in[4];
    const float* b1     = (const float*)d_in[5];
    const float* gamma  = (const float*)d_in[6];
    const float* beta   = (const float*)d_in[7];
    const float* Wc     = (const float*)d_in[8];
    const float* bc     = (const float*)d_in[9];
    float* out = (float*)d_out;

    void* pooled_ptr = nullptr;
    cudaGetSymbolAddress(&pooled_ptr, g_pooled);
    cudaMemsetAsync(pooled_ptr, 0, NB * ND * sizeof(float));

    cudaFuncSetAttribute(gemm_pool_kernel,
                         cudaFuncAttributeMaxDynamicSharedMemorySize, SMEM1_BYTES);
    cudaFuncSetAttribute(bn_cls_kernel,
                         cudaFuncAttributeMaxDynamicSharedMemorySize, NB * ND * 4);

    fix_length_kernel<<<1, 64>>>(length);

    dim3 grid(NT / TB, NB);
    gemm_pool_kernel<<<grid, THREADS, SMEM1_BYTES>>>(body, hand_r, hand_l, W1, b1);
    bn_cls_kernel<<<1, 256, NB * ND * 4>>>((const float*)pooled_ptr, gamma, beta, Wc, bc, out);
}

// round 10
// speedup vs baseline: 1.7358x; 1.1545x over previous
#include <cuda_runtime.h>
#include <cuda_bf16.h>
#include <cstdint>

#define NB 64
#define NT 4096
#define KP 67
#define ND 256
#define NC 7
#define TBM 128            // timesteps per tile = M
#define THREADS 256
#define NSTEPS 9           // 9 k-steps of 16 -> K=144 (134 live + zero pad)
#define KAPAD 148          // fp32 staging row stride (floats)
#define KBPAD 152          // bf16 W row stride: (152*2/4)=76 words, 76%32=12 -> conflict-free frags

__device__ float g_pooled[NB * ND];
__device__ int   g_len[NB];
__device__ int   g_prefix[NB + 1];
__device__ __nv_bfloat16 g_wt_hi[ND * KBPAD];
__device__ __nv_bfloat16 g_wt_lo[ND * KBPAD];

// smem map (bytes from extern base)
#define BS_HI   0
#define BS_LO   (ND * KBPAD * 2)                 // 77824
#define AS_OFF  (2 * ND * KBPAD * 2)             // 155648
#define SMEM_SZ (AS_OFF + TBM * KAPAD * 4)       // 155648 + 75776 = 231424 (<= 232448)

// ---- prologue: dtype-robust length normalize + tile prefix sum ----
__global__ void fix_length_kernel(const void* __restrict__ lenraw)
{
    const int*       as32 = (const int*)lenraw;
    const long long* as64 = (const long long*)lenraw;
    const int i = threadIdx.x;            // 0..63
    int v32 = as32[i];
    bool ok = (v32 >= 1 && v32 <= NT);
    unsigned lo = __ballot_sync(0xffffffffu, i < 32 ? ok : true);
    unsigned hi = __ballot_sync(0xffffffffu, i >= 32 ? ok : true);
    __shared__ unsigned s_lo, s_hi;
    __shared__ int s_len[NB];
    if (i == 0)  s_lo = lo;
    if (i == 32) s_hi = hi;
    __syncthreads();
    bool all32 = (s_lo == 0xffffffffu) && (s_hi == 0xffffffffu);
    int len = all32 ? v32 : (int)as64[i];
    g_len[i] = len;
    s_len[i] = len;
    __syncthreads();
    if (i == 0) {
        int acc = 0;
        for (int k = 0; k < NB; k++) { g_prefix[k] = acc; acc += (s_len[k] + TBM - 1) / TBM; }
        g_prefix[NB] = acc;
    }
}

// ---- prologue: W1 [134][256] -> Wt_hi/Wt_lo [256][KBPAD] bf16 (transposed, split, padded) ----
__global__ void wsplit_kernel(const float* __restrict__ W1)
{
    int idx = blockIdx.x * 256 + threadIdx.x;
    if (idx >= ND * KBPAD) return;
    int n = idx / KBPAD;
    int k = idx - n * KBPAD;
    float v = (k < 2 * KP) ? W1[k * ND + n] : 0.0f;
    __nv_bfloat16 h = __float2bfloat16(v);
    __nv_bfloat16 l = __float2bfloat16(v - __bfloat162float(h));
    g_wt_hi[idx] = h;
    g_wt_lo[idx] = l;
}

__device__ __forceinline__ void bsplit(float2 f, uint32_t& h, uint32_t& l)
{
    __nv_bfloat162 hh = __floats2bfloat162_rn(f.x, f.y);   // .x in low 16 bits
    float rx = f.x - __bfloat162float(hh.x);
    float ry = f.y - __bfloat162float(hh.y);
    __nv_bfloat162 ll = __floats2bfloat162_rn(rx, ry);
    h = *(uint32_t*)&hh;
    l = *(uint32_t*)&ll;
}

// one split-product pass: 9 k-steps x 16 n-tiles of m16n8k16 HMMA
#define MMA_BLOCK(AA, BSP) do {                                                        \
    _Pragma("unroll")                                                                  \
    for (int ks = 0; ks < NSTEPS; ks++) {                                              \
        const __nv_bfloat16* bp = (BSP) + (base_n + g) * KBPAD + ks * 16 + 2 * t;      \
        _Pragma("unroll")                                                              \
        for (int nt = 0; nt < 16; nt++) {                                              \
            uint32_t b0 = *(const uint32_t*)(bp + nt * 8 * KBPAD);                     \
            uint32_t b1v = *(const uint32_t*)(bp + nt * 8 * KBPAD + 8);                \
            asm volatile("mma.sync.aligned.m16n8k16.row.col.f32.bf16.bf16.f32 "        \
                "{%0,%1,%2,%3}, {%4,%5,%6,%7}, {%8,%9}, {%0,%1,%2,%3};"                \
                : "+f"(acc[nt][0]), "+f"(acc[nt][1]), "+f"(acc[nt][2]), "+f"(acc[nt][3]) \
                : "r"((AA)[ks][0]), "r"((AA)[ks][1]), "r"((AA)[ks][2]), "r"((AA)[ks][3]), \
                  "r"(b0), "r"(b1v));                                                  \
        }                                                                              \
    }                                                                                  \
} while (0)

__global__ __launch_bounds__(THREADS, 1)
void gemm_pool_kernel(const float* __restrict__ body,
                      const float* __restrict__ hand_r,
                      const float* __restrict__ hand_l,
                      const float* __restrict__ b1)
{
    extern __shared__ char sm[];
    __nv_bfloat16* BsH = (__nv_bfloat16*)(sm + BS_HI);
    __nv_bfloat16* BsL = (__nv_bfloat16*)(sm + BS_LO);
    float*         As  = (float*)(sm + AS_OFF);

    const int tid = threadIdx.x;
    const int wid = tid >> 5;
    const int lid = tid & 31;
    const int g   = lid >> 2;         // 0..7
    const int t   = lid & 3;          // 0..3

    // ---- load W hi/lo into smem once (linear copy, coalesced) ----
    {
        const uint4* sh = (const uint4*)g_wt_hi;
        const uint4* sl = (const uint4*)g_wt_lo;
        uint4* dh = (uint4*)BsH;
        uint4* dl = (uint4*)BsL;
        const int n16 = ND * KBPAD * 2 / 16;      // 4864
        for (int i = tid; i < n16; i += THREADS) { dh[i] = sh[i]; dl[i] = sl[i]; }
    }

    const int G = g_prefix[NB];

    #pragma unroll 1
    for (int gid = blockIdx.x; gid < G; gid += gridDim.x) {
        // decode (b, t0): binary search on prefix
        int b = 0;
        #pragma unroll
        for (int step = 32; step; step >>= 1)
            if (g_prefix[b + step] <= gid) b += step;
        const int t0  = (gid - g_prefix[b]) * TBM;
        const int len = g_len[b];

        __syncthreads();   // prior iteration done reading staging

        // ---- build gated fp32 staging [128][KAPAD] ----
        for (int idx = tid; idx < TBM * KP; idx += THREADS) {
            int r = idx / KP;
            int j = idx - r * KP;
            int tt = t0 + r;
            const float* src;
            if (j < 25)       src = body   + ((size_t)b * NT + tt) * 75 + 3 * j;
            else if (j < 46)  src = hand_r + ((size_t)b * NT + tt) * 63 + 3 * (j - 25);
            else              src = hand_l + ((size_t)b * NT + tt) * 63 + 3 * (j - 46);
            float x = src[0], y = src[1], c = src[2];
            float gg = (c > 0.1f) ? 1.0f : 0.0f;
            As[r * KAPAD + 2 * j]     = x * gg;
            As[r * KAPAD + 2 * j + 1] = y * gg;
        }
        for (int idx = tid; idx < TBM * (KAPAD - 2 * KP); idx += THREADS) {
            int r = idx / (KAPAD - 2 * KP);
            int c = idx - r * (KAPAD - 2 * KP);
            As[r * KAPAD + 2 * KP + c] = 0.0f;
        }
        __syncthreads();

        // ---- extract A fragments (hi/lo) into registers ----
        const int m0 = wid * 16 + g;
        uint32_t a_hi[NSTEPS][4], a_lo[NSTEPS][4];
        #pragma unroll
        for (int ks = 0; ks < NSTEPS; ks++) {
            const int kc = ks * 16 + 2 * t;
            float2 f0 = *(const float2*)&As[m0 * KAPAD + kc];
            float2 f1 = *(const float2*)&As[(m0 + 8) * KAPAD + kc];
            float2 f2 = *(const float2*)&As[m0 * KAPAD + kc + 8];
            float2 f3 = *(const float2*)&As[(m0 + 8) * KAPAD + kc + 8];
            bsplit(f0, a_hi[ks][0], a_lo[ks][0]);
            bsplit(f1, a_hi[ks][1], a_lo[ks][1]);
            bsplit(f2, a_hi[ks][2], a_lo[ks][2]);
            bsplit(f3, a_hi[ks][3], a_lo[ks][3]);
        }

        const bool v0 = (t0 + wid * 16 + g) < len;
        const bool v1 = (t0 + wid * 16 + g + 8) < len;

        // ---- 2 column halves x 3 splits of HMMA, then pool ----
        #pragma unroll 1
        for (int half = 0; half < 2; half++) {
            const int base_n = half * 128;
            float acc[16][4];
            #pragma unroll
            for (int nt = 0; nt < 16; nt++)
                #pragma unroll
                for (int q = 0; q < 4; q++) acc[nt][q] = 0.0f;

            MMA_BLOCK(a_hi, BsH);     // Ah * Wh
            MMA_BLOCK(a_hi, BsL);     // Ah * Wl
            MMA_BLOCK(a_lo, BsH);     // Al * Wh

            #pragma unroll
            for (int nt = 0; nt < 16; nt++) {
                const int col = base_n + nt * 8 + 2 * t;
                float bb0 = __ldg(&b1[col]);
                float bb1 = __ldg(&b1[col + 1]);
                float m0v = fmaxf(v0 ? fmaxf(acc[nt][0] + bb0, 0.0f) : 0.0f,
                                  v1 ? fmaxf(acc[nt][2] + bb0, 0.0f) : 0.0f);
                float m1v = fmaxf(v0 ? fmaxf(acc[nt][1] + bb1, 0.0f) : 0.0f,
                                  v1 ? fmaxf(acc[nt][3] + bb1, 0.0f) : 0.0f);
                #pragma unroll
                for (int mk = 4; mk <= 16; mk <<= 1) {
                    m0v = fmaxf(m0v, __shfl_xor_sync(0xffffffffu, m0v, mk));
                    m1v = fmaxf(m1v, __shfl_xor_sync(0xffffffffu, m1v, mk));
                }
                if (lid < 4) {
                    atomicMax((int*)&g_pooled[b * ND + col],     __float_as_int(m0v));
                    atomicMax((int*)&g_pooled[b * ND + col + 1], __float_as_int(m1v));
                }
            }
        }
    }
}

// ---- BatchNorm (batch stats) + classifier ----
__global__ __launch_bounds__(256, 1)
void bn_cls_kernel(const float* __restrict__ pooled,
                   const float* __restrict__ gamma,
                   const float* __restrict__ beta,
                   const float* __restrict__ Wc,
                   const float* __restrict__ bc,
                   float* __restrict__ out)
{
    extern __shared__ float sbm[];   // [NB][ND]
    const int d = threadIdx.x;

    float v[NB];
    float s = 0.f;
    #pragma unroll
    for (int bb = 0; bb < NB; bb++) { v[bb] = pooled[bb * ND + d]; s += v[bb]; }
    float mean = s * (1.0f / NB);
    float q = 0.f;
    #pragma unroll
    for (int bb = 0; bb < NB; bb++) { float tt = v[bb] - mean; q += tt * tt; }
    float rstd = rsqrtf(q * (1.0f / NB) + 1e-5f);
    float ga = gamma[d], be = beta[d];
    #pragma unroll
    for (int bb = 0; bb < NB; bb++) sbm[bb * ND + d] = (v[bb] - mean) * rstd * ga + be;
    __syncthreads();

    for (int idx = threadIdx.x; idx < NB * NC; idx += 256) {
        int bb = idx / NC, c = idx - bb * NC;
        float sum = bc[c];
        const float* row = &sbm[bb * ND];
        #pragma unroll 8
        for (int dd = 0; dd < ND; dd++) sum += row[dd] * Wc[dd * NC + c];
        out[bb * NC + c] = sum;
    }
}

extern "C" void kernel_launch(void* const* d_in, const int* in_sizes, int n_in,
                              void* d_out, int out_size)
{
    const float* body   = (const float*)d_in[0];
    const float* hand_r = (const float*)d_in[1];
    const float* hand_l = (const float*)d_in[2];
    const void*  length = d_in[3];
    const float* W1     = (const float*)d_in[4];
    const float* b1     = (const float*)d_in[5];
    const float* gamma  = (const float*)d_in[6];
    const float* beta   = (const float*)d_in[7];
    const float* Wc     = (const float*)d_in[8];
    const float* bc     = (const float*)d_in[9];
    float* out = (float*)d_out;

    void* pooled_ptr = nullptr;
    cudaGetSymbolAddress(&pooled_ptr, g_pooled);
    cudaMemsetAsync(pooled_ptr, 0, NB * ND * sizeof(float));

    int nsm = 148;
    cudaDeviceGetAttribute(&nsm, cudaDevAttrMultiProcessorCount, 0);

    cudaFuncSetAttribute(gemm_pool_kernel,
                         cudaFuncAttributeMaxDynamicSharedMemorySize, SMEM_SZ);
    cudaFuncSetAttribute(bn_cls_kernel,
                         cudaFuncAttributeMaxDynamicSharedMemorySize, NB * ND * 4);

    fix_length_kernel<<<1, 64>>>(length);
    wsplit_kernel<<<(ND * KBPAD + 255) / 256, 256>>>(W1);
    gemm_pool_kernel<<<nsm, THREADS, SMEM_SZ>>>(body, hand_r, hand_l, b1);
    bn_cls_kernel<<<1, 256, NB * ND * 4>>>((const float*)pooled_ptr, gamma, beta, Wc, bc, out);
}

// round 11
// speedup vs baseline: 4.5903x; 2.6446x over previous
#include <cuda_runtime.h>
#include <cuda_bf16.h>
#include <cstdint>

#define NB 64
#define NT 4096
#define KP 67
#define ND 256
#define NC 7
#define THREADS 256
#define NSTEPS 9           // 9 k-steps of 16 -> K=144 (134 live + zero pad)
#define KBPAD 152          // bf16 W row stride -> LDSM conflict-free (304B = 19*16B)
#define UROWS 16           // rows per warp unit

__device__ float g_pooled[NB * ND];
__device__ int   g_len[NB];
__device__ int   g_prefix[NB + 1];
__device__ __nv_bfloat16 g_wt_hi[ND * KBPAD];
__device__ __nv_bfloat16 g_wt_lo[ND * KBPAD];

// smem map (bytes)
#define SW_HI   0
#define SW_LO   (ND * KBPAD * 2)                 // 77824
#define SP_OFF  (2 * ND * KBPAD * 2)             // 155648: prefix[65] + len[64]
#define SMEM_SZ (SP_OFF + 129 * 4)

// ---- prologue: dtype-robust length normalize + unit prefix sum ----
__global__ void fix_length_kernel(const void* __restrict__ lenraw)
{
    const int*       as32 = (const int*)lenraw;
    const long long* as64 = (const long long*)lenraw;
    const int i = threadIdx.x;            // 0..63
    int v32 = as32[i];
    bool ok = (v32 >= 1 && v32 <= NT);
    unsigned lo = __ballot_sync(0xffffffffu, i < 32 ? ok : true);
    unsigned hi = __ballot_sync(0xffffffffu, i >= 32 ? ok : true);
    __shared__ unsigned s_lo, s_hi;
    __shared__ int s_len[NB];
    if (i == 0)  s_lo = lo;
    if (i == 32) s_hi = hi;
    __syncthreads();
    bool all32 = (s_lo == 0xffffffffu) && (s_hi == 0xffffffffu);
    int len = all32 ? v32 : (int)as64[i];
    g_len[i] = len;
    s_len[i] = len;
    __syncthreads();
    if (i == 0) {
        int acc = 0;
        for (int k = 0; k < NB; k++) { g_prefix[k] = acc; acc += (s_len[k] + UROWS - 1) / UROWS; }
        g_prefix[NB] = acc;
    }
}

// ---- prologue: W1 [134][256] -> Wt_hi/Wt_lo [256][KBPAD] bf16 (transposed, split, padded) ----
__global__ void wsplit_kernel(const float* __restrict__ W1)
{
    int idx = blockIdx.x * 256 + threadIdx.x;
    if (idx >= ND * KBPAD) return;
    int n = idx / KBPAD;
    int k = idx - n * KBPAD;
    float v = (k < 2 * KP) ? W1[k * ND + n] : 0.0f;
    __nv_bfloat16 h = __float2bfloat16(v);
    __nv_bfloat16 l = __float2bfloat16(v - __bfloat162float(h));
    g_wt_hi[idx] = h;
    g_wt_lo[idx] = l;
}

__device__ __forceinline__ void bsplit(float2 f, uint32_t& h, uint32_t& l)
{
    __nv_bfloat162 hh = __floats2bfloat162_rn(f.x, f.y);   // .x in low 16 bits
    float rx = f.x - __bfloat162float(hh.x);
    float ry = f.y - __bfloat162float(hh.y);
    __nv_bfloat162 ll = __floats2bfloat162_rn(rx, ry);
    h = *(uint32_t*)&hh;
    l = *(uint32_t*)&ll;
}

__device__ __forceinline__ float2 load_gated(const float* __restrict__ body,
                                             const float* __restrict__ hand_r,
                                             const float* __restrict__ hand_l,
                                             int b, int t, int j)
{
    const float* src;
    if (j < 25)       src = body   + ((size_t)b * NT + t) * 75 + 3 * j;
    else if (j < 46)  src = hand_r + ((size_t)b * NT + t) * 63 + 3 * (j - 25);
    else              src = hand_l + ((size_t)b * NT + t) * 63 + 3 * (j - 46);
    float x = src[0], y = src[1], c = src[2];
    float g = (c > 0.1f) ? 1.0f : 0.0f;
    return make_float2(x * g, y * g);
}

#define LDSM4(d0, d1, d2, d3, addr)                                              \
    asm volatile("ldmatrix.sync.aligned.m8n8.x4.shared.b16 {%0,%1,%2,%3}, [%4];" \
                 : "=r"(d0), "=r"(d1), "=r"(d2), "=r"(d3) : "r"(addr))

#define HMMA(ACC, A, B0, B1)                                                  \
    asm volatile("mma.sync.aligned.m16n8k16.row.col.f32.bf16.bf16.f32 "       \
                 "{%0,%1,%2,%3}, {%4,%5,%6,%7}, {%8,%9}, {%0,%1,%2,%3};"      \
                 : "+f"((ACC)[0]), "+f"((ACC)[1]), "+f"((ACC)[2]), "+f"((ACC)[3]) \
                 : "r"((A)[0]), "r"((A)[1]), "r"((A)[2]), "r"((A)[3]),        \
                   "r"(B0), "r"(B1))

__device__ __forceinline__ uint32_t smem_u32(const void* p) {
    uint32_t a;
    asm("{ .reg .u64 t; cvta.to.shared.u64 t, %1; cvt.u32.u64 %0, t; }" : "=r"(a) : "l"(p));
    return a;
}

__global__ __launch_bounds__(THREADS, 1)
void gemm_pool_kernel(const float* __restrict__ body,
                      const float* __restrict__ hand_r,
                      const float* __restrict__ hand_l,
                      const float* __restrict__ b1)
{
    extern __shared__ char sm[];
    __nv_bfloat16* BsH = (__nv_bfloat16*)(sm + SW_HI);
    __nv_bfloat16* BsL = (__nv_bfloat16*)(sm + SW_LO);
    int* s_prefix = (int*)(sm + SP_OFF);          // [65]
    int* s_len    = s_prefix + 65;                // [64]

    const int tid = threadIdx.x;
    const int wid = tid >> 5;
    const int lid = tid & 31;
    const int g   = lid >> 2;          // 0..7  (output row group)
    const int t   = lid & 3;           // 0..3  (k pair)
    const int mid  = lid >> 3;         // ldmatrix matrix id
    const int lrow = lid & 7;          // ldmatrix row within matrix

    // ---- one-time: W hi/lo into smem; prefix+len into smem ----
    {
        const uint4* sh = (const uint4*)g_wt_hi;
        const uint4* sl = (const uint4*)g_wt_lo;
        uint4* dh = (uint4*)BsH;
        uint4* dl = (uint4*)BsL;
        const int n16 = ND * KBPAD * 2 / 16;      // 4864
        for (int i = tid; i < n16; i += THREADS) { dh[i] = sh[i]; dl[i] = sl[i]; }
        if (tid < 65) s_prefix[tid] = g_prefix[tid];
        if (tid < 64) s_len[tid] = g_len[tid];
    }
    __syncthreads();

    const int total_units = s_prefix[NB];
    const int gwarp   = blockIdx.x * (THREADS / 32) + wid;
    const int gstride = gridDim.x * (THREADS / 32);

    // per-lane ldmatrix element offset within a 16-row W block:
    //   rows (mid>>1)*8 + lrow, k half (mid&1)*8
    const uint32_t lane_b_elem = (uint32_t)(((mid >> 1) * 8 + lrow) * KBPAD + (mid & 1) * 8);
    const uint32_t baseH = smem_u32(BsH) + lane_b_elem * 2;
    const uint32_t baseL = smem_u32(BsL) + lane_b_elem * 2;

    #pragma unroll 1
    for (int u = gwarp; u < total_units; u += gstride) {
        // decode (b, t0) from smem prefix
        int b = 0;
        #pragma unroll
        for (int step = 32; step; step >>= 1)
            if (s_prefix[b + step] <= u) b += step;
        const int t0  = (u - s_prefix[b]) * UROWS;
        const int len = s_len[b];
        const int r0  = t0 + g;
        const int r1  = r0 + 8;

        // ---- gather + gate + split A fragments straight from global ----
        uint32_t a_hi[NSTEPS][4], a_lo[NSTEPS][4];
        #pragma unroll
        for (int ks = 0; ks < NSTEPS; ks++) {
            const int j  = ks * 8 + t;
            const int j2 = j + 4;
            float2 p0 = (j  < KP) ? load_gated(body, hand_r, hand_l, b, r0, j)  : make_float2(0.f, 0.f);
            float2 p1 = (j  < KP) ? load_gated(body, hand_r, hand_l, b, r1, j)  : make_float2(0.f, 0.f);
            float2 p2 = (j2 < KP) ? load_gated(body, hand_r, hand_l, b, r0, j2) : make_float2(0.f, 0.f);
            float2 p3 = (j2 < KP) ? load_gated(body, hand_r, hand_l, b, r1, j2) : make_float2(0.f, 0.f);
            bsplit(p0, a_hi[ks][0], a_lo[ks][0]);
            bsplit(p1, a_hi[ks][1], a_lo[ks][1]);
            bsplit(p2, a_hi[ks][2], a_lo[ks][2]);
            bsplit(p3, a_hi[ks][3], a_lo[ks][3]);
        }

        const bool v0 = r0 < len;
        const bool v1 = r1 < len;

        #pragma unroll 1
        for (int half = 0; half < 2; half++) {
            const int base_n = half * 128;
            float acc[16][4];
            #pragma unroll
            for (int nt = 0; nt < 16; nt++)
                #pragma unroll
                for (int q = 0; q < 4; q++) acc[nt][q] = 0.0f;

            #pragma unroll
            for (int ks = 0; ks < NSTEPS; ks++) {
                #pragma unroll
                for (int ntp = 0; ntp < 8; ntp++) {
                    const uint32_t off = (uint32_t)(((base_n + ntp * 16) * KBPAD + ks * 16) * 2);
                    uint32_t bh0, bh1, bh2, bh3, bl0, bl1, bl2, bl3;
                    LDSM4(bh0, bh1, bh2, bh3, baseH + off);
                    LDSM4(bl0, bl1, bl2, bl3, baseL + off);
                    // Ah*Wh + Ah*Wl + Al*Wh (drop Al*Wl)
                    HMMA(acc[2 * ntp],     a_hi[ks], bh0, bh1);
                    HMMA(acc[2 * ntp + 1], a_hi[ks], bh2, bh3);
                    HMMA(acc[2 * ntp],     a_hi[ks], bl0, bl1);
                    HMMA(acc[2 * ntp + 1], a_hi[ks], bl2, bl3);
                    HMMA(acc[2 * ntp],     a_lo[ks], bh0, bh1);
                    HMMA(acc[2 * ntp + 1], a_lo[ks], bh2, bh3);
                }
            }

            // ---- bias + relu + mask + cross-row max + atomicMax ----
            #pragma unroll
            for (int nt = 0; nt < 16; nt++) {
                const int col = base_n + nt * 8 + 2 * t;
                float bb0 = __ldg(&b1[col]);
                float bb1 = __ldg(&b1[col + 1]);
                float m0v = fmaxf(v0 ? fmaxf(acc[nt][0] + bb0, 0.0f) : 0.0f,
                                  v1 ? fmaxf(acc[nt][2] + bb0, 0.0f) : 0.0f);
                float m1v = fmaxf(v0 ? fmaxf(acc[nt][1] + bb1, 0.0f) : 0.0f,
                                  v1 ? fmaxf(acc[nt][3] + bb1, 0.0f) : 0.0f);
                #pragma unroll
                for (int mk = 4; mk <= 16; mk <<= 1) {
                    m0v = fmaxf(m0v, __shfl_xor_sync(0xffffffffu, m0v, mk));
                    m1v = fmaxf(m1v, __shfl_xor_sync(0xffffffffu, m1v, mk));
                }
                if (lid < 4) {
                    atomicMax((int*)&g_pooled[b * ND + col],     __float_as_int(m0v));
                    atomicMax((int*)&g_pooled[b * ND + col + 1], __float_as_int(m1v));
                }
            }
        }
    }
}

// ---- BatchNorm (batch stats) + classifier (Wc staged in smem) ----
__global__ __launch_bounds__(256, 1)
void bn_cls_kernel(const float* __restrict__ pooled,
                   const float* __restrict__ gamma,
                   const float* __restrict__ beta,
                   const float* __restrict__ Wc,
                   const float* __restrict__ bc,
                   float* __restrict__ out)
{
    extern __shared__ float sbm[];   // [NB][ND] then sWc [ND][NC]
    float* sWc = sbm + NB * ND;
    const int d = threadIdx.x;

    for (int i = threadIdx.x; i < ND * NC; i += 256) sWc[i] = Wc[i];

    float v[NB];
    float s = 0.f;
    #pragma unroll
    for (int bb = 0; bb < NB; bb++) { v[bb] = pooled[bb * ND + d]; s += v[bb]; }
    float mean = s * (1.0f / NB);
    float q = 0.f;
    #pragma unroll
    for (int bb = 0; bb < NB; bb++) { float tt = v[bb] - mean; q += tt * tt; }
    float rstd = rsqrtf(q * (1.0f / NB) + 1e-5f);
    float ga = gamma[d], be = beta[d];
    #pragma unroll
    for (int bb = 0; bb < NB; bb++) sbm[bb * ND + d] = (v[bb] - mean) * rstd * ga + be;
    __syncthreads();

    for (int idx = threadIdx.x; idx < NB * NC; idx += 256) {
        int bb = idx / NC, c = idx - bb * NC;
        float sum = bc[c];
        const float* row = &sbm[bb * ND];
        #pragma unroll 8
        for (int dd = 0; dd < ND; dd++) sum += row[dd] * sWc[dd * NC + c];
        out[bb * NC + c] = sum;
    }
}

extern "C" void kernel_launch(void* const* d_in, const int* in_sizes, int n_in,
                              void* d_out, int out_size)
{
    const float* body   = (const float*)d_in[0];
    const float* hand_r = (const float*)d_in[1];
    const float* hand_l = (const float*)d_in[2];
    const void*  length = d_in[3];
    const float* W1     = (const float*)d_in[4];
    const float* b1     = (const float*)d_in[5];
    const float* gamma  = (const float*)d_in[6];
    const float* beta   = (const float*)d_in[7];
    const float* Wc     = (const float*)d_in[8];
    const float* bc     = (const float*)d_in[9];
    float* out = (float*)d_out;

    void* pooled_ptr = nullptr;
    cudaGetSymbolAddress(&pooled_ptr, g_pooled);
    cudaMemsetAsync(pooled_ptr, 0, NB * ND * sizeof(float));

    int nsm = 148;
    cudaDeviceGetAttribute(&nsm, cudaDevAttrMultiProcessorCount, 0);

    cudaFuncSetAttribute(gemm_pool_kernel,
                         cudaFuncAttributeMaxDynamicSharedMemorySize, SMEM_SZ);
    cudaFuncSetAttribute(bn_cls_kernel,
                         cudaFuncAttributeMaxDynamicSharedMemorySize,
                         (NB * ND + ND * NC) * 4);

    fix_length_kernel<<<1, 64>>>(length);
    wsplit_kernel<<<(ND * KBPAD + 255) / 256, 256>>>(W1);
    gemm_pool_kernel<<<nsm, THREADS, SMEM_SZ>>>(body, hand_r, hand_l, b1);
    bn_cls_kernel<<<1, 256, (NB * ND + ND * NC) * 4>>>((const float*)pooled_ptr,
                                                       gamma, beta, Wc, bc, out);
}